// round 7
// baseline (speedup 1.0000x reference)
#include <cuda_runtime.h>
#include <cstdint>

// Problem constants: B=2, H=16, S=2048, D=64, fp32 in/out.
#define S_LEN   2048
#define D_DIM   64
#define BH_CNT  32
#define BR      128         // Q rows per block (8 warps x 16 rows)
#define BC      64          // KV rows per tile
#define N_TILES (S_LEN / BC)
#define KPAD    68          // staging K row stride: (4g+tig)%32 injective -> conflict-free reads
#define VPAD    72          // staging V row stride: (8tig+g)%32 injective -> conflict-free reads
#define TILE_K  (BC * KPAD) // 4352 floats
#define TILE_V  (BC * VPAD) // 4608 floats
// smem map (float/u32 units):
//   [0, 2*TILE_K)                    staging K, double buffered (fp32)
//   [2*TILE_K, 2*TILE_K+2*TILE_V)    staging V, double buffered (fp32)
//   [FRAG_K, FRAG_K+4096)            K fragments, tf32 bits, fragment-major (u32)
//   [FRAG_V, FRAG_V+4096)            V fragments, tf32 bits, fragment-major (u32)
#define VOFF    (2 * TILE_K)
#define FRAG_K  (2 * TILE_K + 2 * TILE_V)   // 17920
#define FRAG_V  (FRAG_K + 4096)
#define SMEM_WORDS (FRAG_V + 4096)          // 26112
#define SMEM_BYTES (SMEM_WORDS * 4)         // 104448

__device__ __forceinline__ uint32_t f2tf32(float f) {
    uint32_t r;
    asm("cvt.rna.tf32.f32 %0, %1;" : "=r"(r) : "f"(f));
    return r;
}

__device__ __forceinline__ float ex2(float x) {
    float r;
    asm("ex2.approx.f32 %0, %1;" : "=f"(r) : "f"(x));
    return r;
}

__device__ __forceinline__ void mma_tf32(float d[4], const uint32_t a[4],
                                         uint32_t b0, uint32_t b1) {
    asm volatile(
        "mma.sync.aligned.m16n8k8.row.col.f32.tf32.tf32.f32 "
        "{%0,%1,%2,%3}, {%4,%5,%6,%7}, {%8,%9}, {%0,%1,%2,%3};\n"
        : "+f"(d[0]), "+f"(d[1]), "+f"(d[2]), "+f"(d[3])
        : "r"(a[0]), "r"(a[1]), "r"(a[2]), "r"(a[3]), "r"(b0), "r"(b1));
}

__device__ __forceinline__ void cp_async16(void* sdst, const void* gsrc) {
    uint32_t s = (uint32_t)__cvta_generic_to_shared(sdst);
    asm volatile("cp.async.cg.shared.global [%0], [%1], 16;\n" :: "r"(s), "l"(gsrc));
}

// 256 threads: stage one 64x64 K tile + one 64x64 V tile (fp32) via cp.async.
__device__ __forceinline__ void load_tile(float* sK, float* sV,
                                          const float* gK, const float* gV, int tid) {
    #pragma unroll
    for (int i = 0; i < 4; i++) {
        int idx = tid + i * 256;
        int r = idx >> 4;
        int c = (idx & 15) << 2;
        cp_async16(sK + r * KPAD + c, gK + r * D_DIM + c);
    }
    #pragma unroll
    for (int i = 0; i < 4; i++) {
        int idx = tid + i * 256;
        int r = idx >> 4;
        int c = (idx & 15) << 2;
        cp_async16(sV + r * VPAD + c, gV + r * D_DIM + c);
    }
}

// Once-per-tile: fp32 staging -> tf32 bits in fragment-major layout.
// K frag (kt,nt): b0=K[nt*8+g][kt*8+tig], b1=+4 col.
// V frag (kt,nt): b0=V[kt*8+tig][nt*8+g], b1=+4 row.
// Pair layout: slot s = fragpair*32+lane holds {b0(2np),b1(2np),b0(2np+1),b1(2np+1)} as uint4.
__device__ __forceinline__ void convert_tile(const float* stK, const float* stV,
                                             uint32_t* sKf, uint32_t* sVf, int tid) {
    #pragma unroll
    for (int i = 0; i < 4; i++) {
        int s  = tid + i * 256;       // 0..1023
        int l  = s & 31;
        int fp = s >> 5;              // fragpair: kt*4+np
        int kt = fp >> 2, np = fp & 3;
        int gg = l >> 2,  tg = l & 3;

        const float* kr0 = stK + (np * 16 + gg) * KPAD + kt * 8 + tg;
        const float* kr1 = kr0 + 8 * KPAD;
        uint4 wk;
        wk.x = f2tf32(kr0[0]); wk.y = f2tf32(kr0[4]);
        wk.z = f2tf32(kr1[0]); wk.w = f2tf32(kr1[4]);
        *reinterpret_cast<uint4*>(sKf + s * 4) = wk;

        const float* vr0 = stV + (kt * 8 + tg) * VPAD + np * 16 + gg;
        const float* vr1 = vr0 + 4 * VPAD;
        uint4 wv;
        wv.x = f2tf32(vr0[0]); wv.y = f2tf32(vr1[0]);
        wv.z = f2tf32(vr0[8]); wv.w = f2tf32(vr1[8]);
        *reinterpret_cast<uint4*>(sVf + s * 4) = wv;
    }
}

__global__ void __launch_bounds__(256, 2)
attn_tf32_kernel(const float* __restrict__ q, const float* __restrict__ k,
                 const float* __restrict__ v, float* __restrict__ out) {
    extern __shared__ float smem[];
    uint32_t* sKf = reinterpret_cast<uint32_t*>(smem + FRAG_K);
    uint32_t* sVf = reinterpret_cast<uint32_t*>(smem + FRAG_V);

    const int tid  = threadIdx.x;
    const int bh   = blockIdx.y;
    const int lane = tid & 31;
    const int wp   = tid >> 5;
    const int g    = lane >> 2;
    const int tig  = lane & 3;

    const float* kb = k + (size_t)bh * (S_LEN * D_DIM);
    const float* vb = v + (size_t)bh * (S_LEN * D_DIM);

    load_tile(smem, smem + VOFF, kb, vb, tid);
    asm volatile("cp.async.commit_group;\n" ::: "memory");

    // Q fragments, pre-scaled by log2(e)/sqrt(D) -> softmax in base-2 domain.
    const int r0 = blockIdx.x * BR + wp * 16 + g;
    const float* qb = q + (size_t)bh * (S_LEN * D_DIM);
    const float scale = 0.125f * 1.4426950408889634f;
    uint32_t qa[8][4];
    #pragma unroll
    for (int kt = 0; kt < 8; kt++) {
        int c = kt * 8 + tig;
        qa[kt][0] = f2tf32(qb[r0       * D_DIM + c]     * scale);
        qa[kt][1] = f2tf32(qb[(r0 + 8) * D_DIM + c]     * scale);
        qa[kt][2] = f2tf32(qb[r0       * D_DIM + c + 4] * scale);
        qa[kt][3] = f2tf32(qb[(r0 + 8) * D_DIM + c + 4] * scale);
    }

    float o[8][4];
    #pragma unroll
    for (int nt = 0; nt < 8; nt++) { o[nt][0] = o[nt][1] = o[nt][2] = o[nt][3] = 0.f; }
    float m0 = -1e30f, m1 = -1e30f, l0 = 0.f, l1 = 0.f;

    const int srcA = (lane & ~3) | (tig >> 1);
    const int srcB = srcA + 2;
    const bool odd = (tig & 1);

    for (int t = 0; t < N_TILES; t++) {
        if (t + 1 < N_TILES) {
            load_tile(smem + ((t + 1) & 1) * TILE_K,
                      smem + VOFF + ((t + 1) & 1) * TILE_V,
                      kb + (t + 1) * BC * D_DIM, vb + (t + 1) * BC * D_DIM, tid);
            asm volatile("cp.async.commit_group;\n" ::: "memory");
            asm volatile("cp.async.wait_group 1;\n" ::: "memory");
        } else {
            asm volatile("cp.async.wait_group 0;\n" ::: "memory");
        }
        __syncthreads();   // staging(t) visible; frag bufs free (compute(t-1) done)

        convert_tile(smem + (t & 1) * TILE_K, smem + VOFF + (t & 1) * TILE_V,
                     sKf, sVf, tid);
        __syncthreads();   // frags ready

        // ---- S = Q K^T : 64 MMA, fragments via conflict-free LDS.128 (no CVT).
        float s[8][4];
        #pragma unroll
        for (int nt = 0; nt < 8; nt++)
            s[nt][0] = s[nt][1] = s[nt][2] = s[nt][3] = 0.f;
        #pragma unroll
        for (int kt = 0; kt < 8; kt++) {
            #pragma unroll
            for (int np = 0; np < 4; np++) {
                uint4 b = *reinterpret_cast<const uint4*>(
                    sKf + ((kt * 4 + np) * 32 + lane) * 4);
                mma_tf32(s[2 * np],     qa[kt], b.x, b.y);
                mma_tf32(s[2 * np + 1], qa[kt], b.z, b.w);
            }
        }

        // ---- Online softmax (base-2 domain).
        float a0 = -1e30f, a1 = -1e30f;
        #pragma unroll
        for (int nt = 0; nt < 8; nt++) {
            a0 = fmaxf(a0, fmaxf(s[nt][0], s[nt][1]));
            a1 = fmaxf(a1, fmaxf(s[nt][2], s[nt][3]));
        }
        a0 = fmaxf(a0, __shfl_xor_sync(0xffffffffu, a0, 1));
        a0 = fmaxf(a0, __shfl_xor_sync(0xffffffffu, a0, 2));
        a1 = fmaxf(a1, __shfl_xor_sync(0xffffffffu, a1, 1));
        a1 = fmaxf(a1, __shfl_xor_sync(0xffffffffu, a1, 2));
        float mn0 = fmaxf(m0, a0), mn1 = fmaxf(m1, a1);
        float f0 = ex2(m0 - mn0), f1 = ex2(m1 - mn1);
        m0 = mn0; m1 = mn1;

        float rs0 = 0.f, rs1 = 0.f;
        #pragma unroll
        for (int nt = 0; nt < 8; nt++) {
            s[nt][0] = ex2(s[nt][0] - m0); rs0 += s[nt][0];
            s[nt][1] = ex2(s[nt][1] - m0); rs0 += s[nt][1];
            s[nt][2] = ex2(s[nt][2] - m1); rs1 += s[nt][2];
            s[nt][3] = ex2(s[nt][3] - m1); rs1 += s[nt][3];
        }
        rs0 += __shfl_xor_sync(0xffffffffu, rs0, 1);
        rs0 += __shfl_xor_sync(0xffffffffu, rs0, 2);
        rs1 += __shfl_xor_sync(0xffffffffu, rs1, 1);
        rs1 += __shfl_xor_sync(0xffffffffu, rs1, 2);
        l0 = l0 * f0 + rs0;
        l1 = l1 * f1 + rs1;

        #pragma unroll
        for (int nt = 0; nt < 8; nt++) {
            o[nt][0] *= f0; o[nt][1] *= f0;
            o[nt][2] *= f1; o[nt][3] *= f1;
        }

        // ---- O += P V : C->A permutation via intra-quad shuffles, V frags via LDS.128.
        #pragma unroll
        for (int kt = 0; kt < 8; kt++) {
            float v00 = __shfl_sync(0xffffffffu, s[kt][0], srcA);
            float v01 = __shfl_sync(0xffffffffu, s[kt][1], srcA);
            float v10 = __shfl_sync(0xffffffffu, s[kt][2], srcA);
            float v11 = __shfl_sync(0xffffffffu, s[kt][3], srcA);
            float w00 = __shfl_sync(0xffffffffu, s[kt][0], srcB);
            float w01 = __shfl_sync(0xffffffffu, s[kt][1], srcB);
            float w10 = __shfl_sync(0xffffffffu, s[kt][2], srcB);
            float w11 = __shfl_sync(0xffffffffu, s[kt][3], srcB);
            uint32_t pa[4];
            pa[0] = f2tf32(odd ? v01 : v00);
            pa[1] = f2tf32(odd ? v11 : v10);
            pa[2] = f2tf32(odd ? w01 : w00);
            pa[3] = f2tf32(odd ? w11 : w10);
            #pragma unroll
            for (int np = 0; np < 4; np++) {
                uint4 b = *reinterpret_cast<const uint4*>(
                    sVf + ((kt * 4 + np) * 32 + lane) * 4);
                mma_tf32(o[2 * np],     pa, b.x, b.y);
                mma_tf32(o[2 * np + 1], pa, b.z, b.w);
            }
        }
    }

    // ---- Epilogue.
    float inv0 = 1.0f / l0, inv1 = 1.0f / l1;
    float* ob = out + (size_t)bh * (S_LEN * D_DIM);
    #pragma unroll
    for (int nt = 0; nt < 8; nt++) {
        float2 w0 = make_float2(o[nt][0] * inv0, o[nt][1] * inv0);
        float2 w1 = make_float2(o[nt][2] * inv1, o[nt][3] * inv1);
        *reinterpret_cast<float2*>(ob + r0       * D_DIM + nt * 8 + 2 * tig) = w0;
        *reinterpret_cast<float2*>(ob + (r0 + 8) * D_DIM + nt * 8 + 2 * tig) = w1;
    }
}

extern "C" void kernel_launch(void* const* d_in, const int* in_sizes, int n_in,
                              void* d_out, int out_size) {
    (void)in_sizes; (void)n_in; (void)out_size;
    const float* q = (const float*)d_in[0];
    const float* k = (const float*)d_in[1];
    const float* v = (const float*)d_in[2];
    float* out = (float*)d_out;

    cudaFuncSetAttribute(attn_tf32_kernel,
                         cudaFuncAttributeMaxDynamicSharedMemorySize, SMEM_BYTES);

    dim3 grid(S_LEN / BR, BH_CNT);
    attn_tf32_kernel<<<grid, 256, SMEM_BYTES>>>(q, k, v, out);
}

// round 10
// speedup vs baseline: 1.1187x; 1.1187x over previous
#include <cuda_runtime.h>
#include <cstdint>

// Problem constants: B=2, H=16, S=2048, D=64, fp32 in/out.
#define S_LEN   2048
#define D_DIM   64
#define BH_CNT  32
#define BR      256         // Q rows per block (8 warps x 32 rows, 2 m16 tiles each)
#define BC      64          // KV rows per tile
#define N_TILES (S_LEN / BC)
#define KPAD    68          // staging K row stride: conflict-free convert reads
#define VPAD    72          // staging V row stride: conflict-free convert reads
#define TILE_K  (BC * KPAD) // 4352 floats
#define TILE_V  (BC * VPAD) // 4608 floats
// smem map (float/u32 units):
//   [0, 2*TILE_K)                   staging K, double buffered (fp32)
//   [VOFF, VOFF+2*TILE_V)           staging V, double buffered (fp32)
//   [FRAG_K, +8192)                 K fragments tf32, double buffered (u32)
//   [FRAG_V, +8192)                 V fragments tf32, double buffered (u32)
#define VOFF    (2 * TILE_K)
#define FRAG_K  (2 * TILE_K + 2 * TILE_V)   // 17920
#define FRAG_V  (FRAG_K + 8192)
#define SMEM_WORDS (FRAG_V + 8192)          // 34304
#define SMEM_BYTES (SMEM_WORDS * 4)         // 137216

__device__ __forceinline__ uint32_t f2tf32(float f) {
    uint32_t r;
    asm("cvt.rna.tf32.f32 %0, %1;" : "=r"(r) : "f"(f));
    return r;
}

__device__ __forceinline__ float ex2(float x) {
    float r;
    asm("ex2.approx.f32 %0, %1;" : "=f"(r) : "f"(x));
    return r;
}

__device__ __forceinline__ void mma_tf32(float d[4], const uint32_t a[4],
                                         uint32_t b0, uint32_t b1) {
    asm volatile(
        "mma.sync.aligned.m16n8k8.row.col.f32.tf32.tf32.f32 "
        "{%0,%1,%2,%3}, {%4,%5,%6,%7}, {%8,%9}, {%0,%1,%2,%3};\n"
        : "+f"(d[0]), "+f"(d[1]), "+f"(d[2]), "+f"(d[3])
        : "r"(a[0]), "r"(a[1]), "r"(a[2]), "r"(a[3]), "r"(b0), "r"(b1));
}

__device__ __forceinline__ void cp_async16(void* sdst, const void* gsrc) {
    uint32_t s = (uint32_t)__cvta_generic_to_shared(sdst);
    asm volatile("cp.async.cg.shared.global [%0], [%1], 16;\n" :: "r"(s), "l"(gsrc));
}

// 256 threads: stage one 64x64 K tile + one 64x64 V tile (fp32) via cp.async.
__device__ __forceinline__ void load_tile(float* sK, float* sV,
                                          const float* gK, const float* gV, int tid) {
    #pragma unroll
    for (int i = 0; i < 4; i++) {
        int idx = tid + i * 256;
        int r = idx >> 4;
        int c = (idx & 15) << 2;
        cp_async16(sK + r * KPAD + c, gK + r * D_DIM + c);
    }
    #pragma unroll
    for (int i = 0; i < 4; i++) {
        int idx = tid + i * 256;
        int r = idx >> 4;
        int c = (idx & 15) << 2;
        cp_async16(sV + r * VPAD + c, gV + r * D_DIM + c);
    }
}

// Once-per-tile: fp32 staging -> tf32 bits in fragment-major layout.
// Slot s = (kt*4+np)*32+lane holds {Kb0(2np),Kb1(2np),Kb0(2np+1),Kb1(2np+1)} as uint4.
__device__ __forceinline__ void convert_tile(const float* stK, const float* stV,
                                             uint32_t* sKf, uint32_t* sVf, int tid) {
    #pragma unroll
    for (int i = 0; i < 4; i++) {
        int s  = tid + i * 256;       // 0..1023
        int l  = s & 31;
        int fp = s >> 5;              // fragpair: kt*4+np
        int kt = fp >> 2, np = fp & 3;
        int gg = l >> 2,  tg = l & 3;

        const float* kr0 = stK + (np * 16 + gg) * KPAD + kt * 8 + tg;
        const float* kr1 = kr0 + 8 * KPAD;
        uint4 wk;
        wk.x = f2tf32(kr0[0]); wk.y = f2tf32(kr0[4]);
        wk.z = f2tf32(kr1[0]); wk.w = f2tf32(kr1[4]);
        *reinterpret_cast<uint4*>(sKf + s * 4) = wk;

        const float* vr0 = stV + (kt * 8 + tg) * VPAD + np * 16 + gg;
        const float* vr1 = vr0 + 4 * VPAD;
        uint4 wv;
        wv.x = f2tf32(vr0[0]); wv.y = f2tf32(vr1[0]);
        wv.z = f2tf32(vr0[8]); wv.w = f2tf32(vr1[8]);
        *reinterpret_cast<uint4*>(sVf + s * 4) = wv;
    }
}

__global__ void __launch_bounds__(256, 1)
attn_tf32_kernel(const float* __restrict__ q, const float* __restrict__ k,
                 const float* __restrict__ v, float* __restrict__ out) {
    extern __shared__ float smem[];
    uint32_t* sKf = reinterpret_cast<uint32_t*>(smem + FRAG_K);
    uint32_t* sVf = reinterpret_cast<uint32_t*>(smem + FRAG_V);

    const int tid  = threadIdx.x;
    const int bh   = blockIdx.y;
    const int lane = tid & 31;
    const int wp   = tid >> 5;
    const int g    = lane >> 2;
    const int tig  = lane & 3;

    const float* kb = k + (size_t)bh * (S_LEN * D_DIM);
    const float* vb = v + (size_t)bh * (S_LEN * D_DIM);

    // Prologue: stage tiles 0 and 1; convert tile 0.
    load_tile(smem, smem + VOFF, kb, vb, tid);
    asm volatile("cp.async.commit_group;\n" ::: "memory");
    load_tile(smem + TILE_K, smem + VOFF + TILE_V,
              kb + BC * D_DIM, vb + BC * D_DIM, tid);
    asm volatile("cp.async.commit_group;\n" ::: "memory");

    // Q fragments for both M-tiles, pre-scaled by log2(e)/sqrt(D).
    const int r0 = blockIdx.x * BR + wp * 32 + g;   // rows r0,r0+8 (t0), r0+16,r0+24 (t1)
    const float* qb = q + (size_t)bh * (S_LEN * D_DIM);
    const float scale = 0.125f * 1.4426950408889634f;
    uint32_t qa0[8][4], qa1[8][4];
    #pragma unroll
    for (int kt = 0; kt < 8; kt++) {
        int c = kt * 8 + tig;
        qa0[kt][0] = f2tf32(qb[r0        * D_DIM + c]     * scale);
        qa0[kt][1] = f2tf32(qb[(r0 +  8) * D_DIM + c]     * scale);
        qa0[kt][2] = f2tf32(qb[r0        * D_DIM + c + 4] * scale);
        qa0[kt][3] = f2tf32(qb[(r0 +  8) * D_DIM + c + 4] * scale);
        qa1[kt][0] = f2tf32(qb[(r0 + 16) * D_DIM + c]     * scale);
        qa1[kt][1] = f2tf32(qb[(r0 + 24) * D_DIM + c]     * scale);
        qa1[kt][2] = f2tf32(qb[(r0 + 16) * D_DIM + c + 4] * scale);
        qa1[kt][3] = f2tf32(qb[(r0 + 24) * D_DIM + c + 4] * scale);
    }

    float o0[8][4], o1[8][4];
    #pragma unroll
    for (int nt = 0; nt < 8; nt++) {
        o0[nt][0] = o0[nt][1] = o0[nt][2] = o0[nt][3] = 0.f;
        o1[nt][0] = o1[nt][1] = o1[nt][2] = o1[nt][3] = 0.f;
    }
    float m0 = -1e30f, m1 = -1e30f, l0 = 0.f, l1 = 0.f;
    float m2 = -1e30f, m3 = -1e30f, l2 = 0.f, l3 = 0.f;

    const int srcA = (lane & ~3) | (tig >> 1);
    const int srcB = srcA + 2;
    const bool odd = (tig & 1);

    // Finish staging(0), convert frags(0).
    asm volatile("cp.async.wait_group 1;\n" ::: "memory");
    __syncthreads();
    convert_tile(smem, smem + VOFF, sKf, sVf, tid);
    __syncthreads();

    for (int t = 0; t < N_TILES; t++) {
        const uint32_t* Kf = sKf + (t & 1) * 4096;
        const uint32_t* Vf = sVf + (t & 1) * 4096;

        // ---- S = Q K^T for both M-tiles: each LDS.128 feeds 4 MMAs.
        float s0[8][4], s1[8][4];
        #pragma unroll
        for (int nt = 0; nt < 8; nt++) {
            s0[nt][0] = s0[nt][1] = s0[nt][2] = s0[nt][3] = 0.f;
            s1[nt][0] = s1[nt][1] = s1[nt][2] = s1[nt][3] = 0.f;
        }
        #pragma unroll
        for (int kt = 0; kt < 8; kt++) {
            #pragma unroll
            for (int np = 0; np < 4; np++) {
                uint4 b = *reinterpret_cast<const uint4*>(
                    Kf + ((kt * 4 + np) * 32 + lane) * 4);
                mma_tf32(s0[2 * np],     qa0[kt], b.x, b.y);
                mma_tf32(s0[2 * np + 1], qa0[kt], b.z, b.w);
                mma_tf32(s1[2 * np],     qa1[kt], b.x, b.y);
                mma_tf32(s1[2 * np + 1], qa1[kt], b.z, b.w);
            }
        }

        // ---- Online softmax (base-2), M-tile 0 (rows g, g+8).
        {
            float a0 = -1e30f, a1 = -1e30f;
            #pragma unroll
            for (int nt = 0; nt < 8; nt++) {
                a0 = fmaxf(a0, fmaxf(s0[nt][0], s0[nt][1]));
                a1 = fmaxf(a1, fmaxf(s0[nt][2], s0[nt][3]));
            }
            a0 = fmaxf(a0, __shfl_xor_sync(0xffffffffu, a0, 1));
            a0 = fmaxf(a0, __shfl_xor_sync(0xffffffffu, a0, 2));
            a1 = fmaxf(a1, __shfl_xor_sync(0xffffffffu, a1, 1));
            a1 = fmaxf(a1, __shfl_xor_sync(0xffffffffu, a1, 2));
            float mn0 = fmaxf(m0, a0), mn1 = fmaxf(m1, a1);
            float f0 = ex2(m0 - mn0), f1 = ex2(m1 - mn1);
            m0 = mn0; m1 = mn1;
            float rs0 = 0.f, rs1 = 0.f;
            #pragma unroll
            for (int nt = 0; nt < 8; nt++) {
                s0[nt][0] = ex2(s0[nt][0] - m0); rs0 += s0[nt][0];
                s0[nt][1] = ex2(s0[nt][1] - m0); rs0 += s0[nt][1];
                s0[nt][2] = ex2(s0[nt][2] - m1); rs1 += s0[nt][2];
                s0[nt][3] = ex2(s0[nt][3] - m1); rs1 += s0[nt][3];
            }
            rs0 += __shfl_xor_sync(0xffffffffu, rs0, 1);
            rs0 += __shfl_xor_sync(0xffffffffu, rs0, 2);
            rs1 += __shfl_xor_sync(0xffffffffu, rs1, 1);
            rs1 += __shfl_xor_sync(0xffffffffu, rs1, 2);
            l0 = l0 * f0 + rs0;
            l1 = l1 * f1 + rs1;
            #pragma unroll
            for (int nt = 0; nt < 8; nt++) {
                o0[nt][0] *= f0; o0[nt][1] *= f0;
                o0[nt][2] *= f1; o0[nt][3] *= f1;
            }
        }
        // ---- Online softmax, M-tile 1 (rows g+16, g+24).
        {
            float a0 = -1e30f, a1 = -1e30f;
            #pragma unroll
            for (int nt = 0; nt < 8; nt++) {
                a0 = fmaxf(a0, fmaxf(s1[nt][0], s1[nt][1]));
                a1 = fmaxf(a1, fmaxf(s1[nt][2], s1[nt][3]));
            }
            a0 = fmaxf(a0, __shfl_xor_sync(0xffffffffu, a0, 1));
            a0 = fmaxf(a0, __shfl_xor_sync(0xffffffffu, a0, 2));
            a1 = fmaxf(a1, __shfl_xor_sync(0xffffffffu, a1, 1));
            a1 = fmaxf(a1, __shfl_xor_sync(0xffffffffu, a1, 2));
            float mn0 = fmaxf(m2, a0), mn1 = fmaxf(m3, a1);
            float f0 = ex2(m2 - mn0), f1 = ex2(m3 - mn1);
            m2 = mn0; m3 = mn1;
            float rs0 = 0.f, rs1 = 0.f;
            #pragma unroll
            for (int nt = 0; nt < 8; nt++) {
                s1[nt][0] = ex2(s1[nt][0] - m2); rs0 += s1[nt][0];
                s1[nt][1] = ex2(s1[nt][1] - m2); rs0 += s1[nt][1];
                s1[nt][2] = ex2(s1[nt][2] - m3); rs1 += s1[nt][2];
                s1[nt][3] = ex2(s1[nt][3] - m3); rs1 += s1[nt][3];
            }
            rs0 += __shfl_xor_sync(0xffffffffu, rs0, 1);
            rs0 += __shfl_xor_sync(0xffffffffu, rs0, 2);
            rs1 += __shfl_xor_sync(0xffffffffu, rs1, 1);
            rs1 += __shfl_xor_sync(0xffffffffu, rs1, 2);
            l2 = l2 * f0 + rs0;
            l3 = l3 * f1 + rs1;
            #pragma unroll
            for (int nt = 0; nt < 8; nt++) {
                o1[nt][0] *= f0; o1[nt][1] *= f0;
                o1[nt][2] *= f1; o1[nt][3] *= f1;
            }
        }

        // ---- O += P V for both M-tiles: each V LDS.128 feeds 4 MMAs.
        #pragma unroll
        for (int kt = 0; kt < 8; kt++) {
            float v00 = __shfl_sync(0xffffffffu, s0[kt][0], srcA);
            float v01 = __shfl_sync(0xffffffffu, s0[kt][1], srcA);
            float v10 = __shfl_sync(0xffffffffu, s0[kt][2], srcA);
            float v11 = __shfl_sync(0xffffffffu, s0[kt][3], srcA);
            float w00 = __shfl_sync(0xffffffffu, s0[kt][0], srcB);
            float w01 = __shfl_sync(0xffffffffu, s0[kt][1], srcB);
            float w10 = __shfl_sync(0xffffffffu, s0[kt][2], srcB);
            float w11 = __shfl_sync(0xffffffffu, s0[kt][3], srcB);
            uint32_t pa0[4];
            pa0[0] = f2tf32(odd ? v01 : v00);
            pa0[1] = f2tf32(odd ? v11 : v10);
            pa0[2] = f2tf32(odd ? w01 : w00);
            pa0[3] = f2tf32(odd ? w11 : w10);
            v00 = __shfl_sync(0xffffffffu, s1[kt][0], srcA);
            v01 = __shfl_sync(0xffffffffu, s1[kt][1], srcA);
            v10 = __shfl_sync(0xffffffffu, s1[kt][2], srcA);
            v11 = __shfl_sync(0xffffffffu, s1[kt][3], srcA);
            w00 = __shfl_sync(0xffffffffu, s1[kt][0], srcB);
            w01 = __shfl_sync(0xffffffffu, s1[kt][1], srcB);
            w10 = __shfl_sync(0xffffffffu, s1[kt][2], srcB);
            w11 = __shfl_sync(0xffffffffu, s1[kt][3], srcB);
            uint32_t pa1[4];
            pa1[0] = f2tf32(odd ? v01 : v00);
            pa1[1] = f2tf32(odd ? v11 : v10);
            pa1[2] = f2tf32(odd ? w01 : w00);
            pa1[3] = f2tf32(odd ? w11 : w10);
            #pragma unroll
            for (int np = 0; np < 4; np++) {
                uint4 b = *reinterpret_cast<const uint4*>(
                    Vf + ((kt * 4 + np) * 32 + lane) * 4);
                mma_tf32(o0[2 * np],     pa0, b.x, b.y);
                mma_tf32(o0[2 * np + 1], pa0, b.z, b.w);
                mma_tf32(o1[2 * np],     pa1, b.x, b.y);
                mma_tf32(o1[2 * np + 1], pa1, b.z, b.w);
            }
        }

        // ---- Pipeline: stage(t+2), finish stage(t+1), convert frags(t+1).
        if (t + 1 < N_TILES) {
            if (t + 2 < N_TILES) {
                load_tile(smem + ((t + 2) & 1) * TILE_K,
                          smem + VOFF + ((t + 2) & 1) * TILE_V,
                          kb + (t + 2) * BC * D_DIM, vb + (t + 2) * BC * D_DIM, tid);
                asm volatile("cp.async.commit_group;\n" ::: "memory");
                asm volatile("cp.async.wait_group 1;\n" ::: "memory");
            } else {
                asm volatile("cp.async.wait_group 0;\n" ::: "memory");
            }
            __syncthreads();   // compute(t) done; staging(t+1) visible to all
            convert_tile(smem + ((t + 1) & 1) * TILE_K,
                         smem + VOFF + ((t + 1) & 1) * TILE_V,
                         sKf + ((t + 1) & 1) * 4096, sVf + ((t + 1) & 1) * 4096, tid);
            __syncthreads();   // frags(t+1) ready
        }
    }

    // ---- Epilogue: O / l, float2 stores, both M-tiles.
    float inv0 = 1.0f / l0, inv1 = 1.0f / l1;
    float inv2 = 1.0f / l2, inv3 = 1.0f / l3;
    float* ob = out + (size_t)bh * (S_LEN * D_DIM);
    #pragma unroll
    for (int nt = 0; nt < 8; nt++) {
        float2 w0 = make_float2(o0[nt][0] * inv0, o0[nt][1] * inv0);
        float2 w1 = make_float2(o0[nt][2] * inv1, o0[nt][3] * inv1);
        float2 w2 = make_float2(o1[nt][0] * inv2, o1[nt][1] * inv2);
        float2 w3 = make_float2(o1[nt][2] * inv3, o1[nt][3] * inv3);
        *reinterpret_cast<float2*>(ob + r0        * D_DIM + nt * 8 + 2 * tig) = w0;
        *reinterpret_cast<float2*>(ob + (r0 +  8) * D_DIM + nt * 8 + 2 * tig) = w1;
        *reinterpret_cast<float2*>(ob + (r0 + 16) * D_DIM + nt * 8 + 2 * tig) = w2;
        *reinterpret_cast<float2*>(ob + (r0 + 24) * D_DIM + nt * 8 + 2 * tig) = w3;
    }
}

extern "C" void kernel_launch(void* const* d_in, const int* in_sizes, int n_in,
                              void* d_out, int out_size) {
    (void)in_sizes; (void)n_in; (void)out_size;
    const float* q = (const float*)d_in[0];
    const float* k = (const float*)d_in[1];
    const float* v = (const float*)d_in[2];
    float* out = (float*)d_out;

    cudaFuncSetAttribute(attn_tf32_kernel,
                         cudaFuncAttributeMaxDynamicSharedMemorySize, SMEM_BYTES);

    dim3 grid(S_LEN / BR, BH_CNT);   // (8, 32)
    attn_tf32_kernel<<<grid, 256, SMEM_BYTES>>>(q, k, v, out);
}